// round 3
// baseline (speedup 1.0000x reference)
#include <cuda_runtime.h>
#include <cstdint>

#define B_  16
#define S_  512
#define H_  128
#define L_  20
#define TS  64          // tile size in s and t per CTA
#define APAD 68         // padded row stride (floats) for transposed smem tiles

// Scratch for reciprocal weighted norms: r[b][l][s] = 1/||w_l . v[b,s]||
__device__ float g_r1[B_ * L_ * S_];
__device__ float g_r2[B_ * L_ * S_];

// ---------------- packed f32x2 helpers (Blackwell sm_100a) ----------------
__device__ __forceinline__ unsigned long long pk2(float lo, float hi) {
    unsigned long long r;
    asm("mov.b64 %0, {%1, %2};" : "=l"(r) : "f"(lo), "f"(hi));
    return r;
}
__device__ __forceinline__ unsigned long long mul2(unsigned long long a, unsigned long long b) {
    unsigned long long r;
    asm("mul.rn.f32x2 %0, %1, %2;" : "=l"(r) : "l"(a), "l"(b));
    return r;
}
__device__ __forceinline__ unsigned long long fma2(unsigned long long a, unsigned long long b,
                                                   unsigned long long c) {
    unsigned long long r;
    asm("fma.rn.f32x2 %0, %1, %2, %3;" : "=l"(r) : "l"(a), "l"(b), "l"(c));
    return r;
}
__device__ __forceinline__ void unpk2(unsigned long long v, float& lo, float& hi) {
    asm("mov.b64 {%0, %1}, %2;" : "=f"(lo), "=f"(hi) : "l"(v));
}

// ---------------- kernel 1: reciprocal weighted norms ----------------
// One warp per (b, s) row. lane holds 4 h-values as float4.
// p_l = sum_h (w[l,h] * v[h])^2 ;  r = rsqrt(p_l)
__global__ void norm_kernel(const float* __restrict__ v,
                            const float* __restrict__ w,
                            int which) {
    float* rg = which ? g_r2 : g_r1;
    const int gwarp = (blockIdx.x * blockDim.x + threadIdx.x) >> 5;
    const int lane  = threadIdx.x & 31;
    if (gwarp >= B_ * S_) return;

    const float4 xv = ((const float4*)(v + (size_t)gwarp * H_))[lane];
    const int b = gwarp >> 9;          // / 512
    const int s = gwarp & (S_ - 1);

    #pragma unroll 1
    for (int l = 0; l < L_; ++l) {
        const float4 wv = ((const float4*)(w + l * H_))[lane];
        const float t0 = wv.x * xv.x;
        const float t1 = wv.y * xv.y;
        const float t2 = wv.z * xv.z;
        const float t3 = wv.w * xv.w;
        float p = t0 * t0 + t1 * t1 + t2 * t2 + t3 * t3;
        #pragma unroll
        for (int o = 16; o; o >>= 1) p += __shfl_xor_sync(0xffffffffu, p, o);
        if (lane == 0)
            rg[((size_t)b * L_ + l) * S_ + s] = rsqrtf(fmaxf(p, 1e-24f));
    }
}

// ---------------- kernel 2: main tiled product ----------------
// CTA: one b, 64 s, 64 t. 256 threads as (16 tx, 16 ty); each thread owns a
// 4s x 4t micro-tile. l processed 2 at a time; i-pairs ride f32x2 lanes.
__global__ void __launch_bounds__(256, 2)
match_kernel(const float* __restrict__ v1, const float* __restrict__ v2,
             const float* __restrict__ w, float* __restrict__ out) {
    extern __shared__ float sm[];
    float* sA  = sm;                     // [H_][APAD] transposed v1 tile
    float* sB  = sA + H_ * APAD;         // [H_][APAD] transposed v2 tile
    float* sW  = sB + H_ * APAD;         // [L_][H_]   w^2
    float* sR1 = sW + L_ * H_;           // [L_][TS]
    float* sR2 = sR1 + L_ * TS;          // [L_][TS]

    const int tx  = threadIdx.x;
    const int ty  = threadIdx.y;
    const int tid = ty * 16 + tx;
    const int b   = blockIdx.z;
    const int s0  = blockIdx.y * TS;
    const int t0  = blockIdx.x * TS;

    const float* v1p = v1 + ((size_t)b * S_ + s0) * H_;
    const float* v2p = v2 + ((size_t)b * S_ + t0) * H_;

    // Fill transposed tiles. f -> (r = f & 63, h4 = f >> 6); consecutive lanes
    // write consecutive smem columns (conflict-free STS).
    for (int f = tid; f < TS * (H_ / 4); f += 256) {
        const int r  = f & (TS - 1);
        const int h4 = f >> 6;
        const float4 va = *(const float4*)(v1p + r * H_ + h4 * 4);
        const float4 vb = *(const float4*)(v2p + r * H_ + h4 * 4);
        const int base = (h4 * 4) * APAD + r;
        sA[base]            = va.x;
        sA[base + APAD]     = va.y;
        sA[base + 2 * APAD] = va.z;
        sA[base + 3 * APAD] = va.w;
        sB[base]            = vb.x;
        sB[base + APAD]     = vb.y;
        sB[base + 2 * APAD] = vb.z;
        sB[base + 3 * APAD] = vb.w;
    }
    for (int i = tid; i < L_ * H_; i += 256) {
        const float wv = w[i];
        sW[i] = wv * wv;
    }
    for (int i = tid; i < L_ * TS; i += 256) {
        const int l  = i >> 6;
        const int ss = i & (TS - 1);
        sR1[i] = g_r1[((size_t)b * L_ + l) * S_ + s0 + ss];
        sR2[i] = g_r2[((size_t)b * L_ + l) * S_ + t0 + ss];
    }
    __syncthreads();

    float* outp = out + (((size_t)b * S_ + s0) * S_ + t0) * L_;

    #pragma unroll 1
    for (int lb = 0; lb < L_; lb += 2) {
        // acc[l-in-pair][i-pair][j] ; f32x2 lanes = (i = 2*ip, i = 2*ip + 1)
        unsigned long long acc[2][2][4];
        #pragma unroll
        for (int a = 0; a < 2; ++a)
            #pragma unroll
            for (int p = 0; p < 2; ++p)
                #pragma unroll
                for (int j = 0; j < 4; ++j) acc[a][p][j] = 0ull;

        const float* w0p = sW + lb * H_;
        const float* w1p = w0p + H_;

        #pragma unroll 4
        for (int h = 0; h < H_; ++h) {
            const float* rowA = sA + h * APAD;
            const ulonglong2 ap = *(const ulonglong2*)(rowA + (ty << 2));
            const float4 bv = *(const float4*)(sB + h * APAD + (tx << 2));

            const unsigned long long bd0 = pk2(bv.x, bv.x);
            const unsigned long long bd1 = pk2(bv.y, bv.y);
            const unsigned long long bd2 = pk2(bv.z, bv.z);
            const unsigned long long bd3 = pk2(bv.w, bv.w);

            const float w0 = w0p[h];
            const float w1 = w1p[h];
            const unsigned long long wp0 = pk2(w0, w0);
            const unsigned long long wp1 = pk2(w1, w1);

            const unsigned long long a0w0 = mul2(ap.x, wp0);
            const unsigned long long a1w0 = mul2(ap.y, wp0);
            const unsigned long long a0w1 = mul2(ap.x, wp1);
            const unsigned long long a1w1 = mul2(ap.y, wp1);

            acc[0][0][0] = fma2(a0w0, bd0, acc[0][0][0]);
            acc[0][0][1] = fma2(a0w0, bd1, acc[0][0][1]);
            acc[0][0][2] = fma2(a0w0, bd2, acc[0][0][2]);
            acc[0][0][3] = fma2(a0w0, bd3, acc[0][0][3]);
            acc[0][1][0] = fma2(a1w0, bd0, acc[0][1][0]);
            acc[0][1][1] = fma2(a1w0, bd1, acc[0][1][1]);
            acc[0][1][2] = fma2(a1w0, bd2, acc[0][1][2]);
            acc[0][1][3] = fma2(a1w0, bd3, acc[0][1][3]);
            acc[1][0][0] = fma2(a0w1, bd0, acc[1][0][0]);
            acc[1][0][1] = fma2(a0w1, bd1, acc[1][0][1]);
            acc[1][0][2] = fma2(a0w1, bd2, acc[1][0][2]);
            acc[1][0][3] = fma2(a0w1, bd3, acc[1][0][3]);
            acc[1][1][0] = fma2(a1w1, bd0, acc[1][1][0]);
            acc[1][1][1] = fma2(a1w1, bd1, acc[1][1][1]);
            acc[1][1][2] = fma2(a1w1, bd2, acc[1][1][2]);
            acc[1][1][3] = fma2(a1w1, bd3, acc[1][1][3]);
        }

        // Epilogue: out = acc * r1[s] * r2[t], scattered l-strided stores
        // (merged in L2; per-CTA out tile stays resident).
        #pragma unroll
        for (int ll = 0; ll < 2; ++ll) {
            const int l = lb + ll;
            float r1v[4], r2v[4];
            #pragma unroll
            for (int k = 0; k < 4; ++k) {
                r1v[k] = sR1[l * TS + (ty << 2) + k];
                r2v[k] = sR2[l * TS + (tx << 2) + k];
            }
            #pragma unroll
            for (int ip = 0; ip < 2; ++ip) {
                #pragma unroll
                for (int j = 0; j < 4; ++j) {
                    float lo, hi;
                    unpk2(acc[ll][ip][j], lo, hi);
                    const int i0 = (ip << 1);
                    const int i1 = i0 + 1;
                    const int sI0 = (ty << 2) + i0;
                    const int tJ  = (tx << 2) + j;
                    outp[((size_t)sI0 * S_ + tJ) * L_ + l]       = lo * r1v[i0] * r2v[j];
                    outp[((size_t)(sI0 + 1) * S_ + tJ) * L_ + l] = hi * r1v[i1] * r2v[j];
                }
            }
        }
    }
}

// ---------------- launch ----------------
extern "C" void kernel_launch(void* const* d_in, const int* in_sizes, int n_in,
                              void* d_out, int out_size) {
    (void)in_sizes; (void)n_in; (void)out_size;
    const float* v1 = (const float*)d_in[0];   // (16, 512, 128)
    const float* v2 = (const float*)d_in[1];   // (16, 512, 128)
    const float* w  = (const float*)d_in[2];   // (20, 128)
    float* out = (float*)d_out;                // (16, 512, 512, 20)

    const size_t SMEM = (size_t)(2 * H_ * APAD + L_ * H_ + 2 * L_ * TS) * sizeof(float); // 90112 B
    cudaFuncSetAttribute(match_kernel, cudaFuncAttributeMaxDynamicSharedMemorySize, (int)SMEM);

    const int nwarps  = B_ * S_;                         // 8192 rows
    const int threads = 256;                             // 8 warps/block
    const int blocks  = (nwarps * 32 + threads - 1) / threads;  // 1024
    norm_kernel<<<blocks, threads>>>(v1, w, 0);
    norm_kernel<<<blocks, threads>>>(v2, w, 1);

    dim3 grid(S_ / TS, S_ / TS, B_);   // (8, 8, 16)
    dim3 blk(16, 16);
    match_kernel<<<grid, blk, SMEM>>>(v1, v2, w, out);
}

// round 5
// speedup vs baseline: 3.0809x; 3.0809x over previous
#include <cuda_runtime.h>
#include <cstdint>

#define B_   16
#define S_   512
#define H_   128
#define L_   20
#define TM   128          // s per CTA
#define TT   64           // t per CTA
#define NCH  160          // MMA N per chunk = 8 t x 20 l (l fastest)
#define NCHUNKS 8
#define STRD 132          // padded smem row stride (words): banks 4r+c, conflict-free

// smem word offsets
#define W_A   (TM * STRD)            // 16896
#define W_B   (NCH * STRD)           // 21120
#define W_V2  (TT * H_)              // 8192
#define W_W2  (L_ * H_)              // 2560
#define W_R1  (L_ * STRD)            // 2640
#define W_R2  (L_ * TT)              // 1280
#define SMEM_WORDS (W_A + W_B + W_V2 + W_W2 + W_R1 + W_R2)   // 52688
#define SMEM_BYTES (SMEM_WORDS * 4)                          // 210752

// reciprocal weighted norms: r[b][l][s] = 1/||w_l . v[b,s]||
__device__ float g_r1[B_ * L_ * S_];
__device__ float g_r2[B_ * L_ * S_];

static __device__ __forceinline__ uint32_t tf32r(float x) {
    uint32_t r;
    asm("cvt.rna.tf32.f32 %0, %1;" : "=r"(r) : "f"(x));
    return r;
}
static __device__ __forceinline__ void mma_tf32(float& c0, float& c1, float& c2, float& c3,
                                                uint32_t a0, uint32_t a1, uint32_t a2, uint32_t a3,
                                                uint32_t b0, uint32_t b1) {
    asm volatile("mma.sync.aligned.m16n8k8.row.col.f32.tf32.tf32.f32 "
                 "{%0,%1,%2,%3}, {%4,%5,%6,%7}, {%8,%9}, {%0,%1,%2,%3};"
                 : "+f"(c0), "+f"(c1), "+f"(c2), "+f"(c3)
                 : "r"(a0), "r"(a1), "r"(a2), "r"(a3), "r"(b0), "r"(b1));
}

// ---------------- kernel 1: reciprocal weighted norms ----------------
__global__ void norm_kernel(const float* __restrict__ v1, const float* __restrict__ v2,
                            const float* __restrict__ w) {
    const float* v  = blockIdx.y ? v2 : v1;
    float*       rg = blockIdx.y ? g_r2 : g_r1;
    const int gwarp = (blockIdx.x * blockDim.x + threadIdx.x) >> 5;
    const int lane  = threadIdx.x & 31;
    if (gwarp >= B_ * S_) return;

    const float4 xv = ((const float4*)(v + (size_t)gwarp * H_))[lane];
    const int b = gwarp >> 9;
    const int s = gwarp & (S_ - 1);

    #pragma unroll
    for (int l = 0; l < L_; l += 2) {
        const float4 w0 = ((const float4*)(w + l * H_))[lane];
        const float4 w1 = ((const float4*)(w + (l + 1) * H_))[lane];
        float t, p0, p1;
        t = w0.x * xv.x; p0  = t * t;  t = w1.x * xv.x; p1  = t * t;
        t = w0.y * xv.y; p0 += t * t;  t = w1.y * xv.y; p1 += t * t;
        t = w0.z * xv.z; p0 += t * t;  t = w1.z * xv.z; p1 += t * t;
        t = w0.w * xv.w; p0 += t * t;  t = w1.w * xv.w; p1 += t * t;
        #pragma unroll
        for (int o = 16; o; o >>= 1) {
            p0 += __shfl_xor_sync(0xffffffffu, p0, o);
            p1 += __shfl_xor_sync(0xffffffffu, p1, o);
        }
        if (lane == 0) {
            rg[((size_t)b * L_ + l) * S_ + s]     = rsqrtf(fmaxf(p0, 1e-24f));
            rg[((size_t)b * L_ + l + 1) * S_ + s] = rsqrtf(fmaxf(p1, 1e-24f));
        }
    }
}

// ---------------- kernel 2: tf32 mma.sync GEMM, l-in-N ----------------
// 256 threads = 8 warps: warp_m = wid>>1 (4 along M), warp_n = wid&1 (2 along N).
// Per warp: 2 m16-tiles x 10 n8-tiles, K=128 in 16 k8 steps.
__global__ void __launch_bounds__(256, 1)
match_kernel(const float* __restrict__ v1, const float* __restrict__ v2,
             const float* __restrict__ w, float* __restrict__ out) {
    extern __shared__ uint32_t smu[];
    uint32_t* sA  = smu;                     // [128][STRD] tf32 bits, row-major (M x K)
    uint32_t* sB  = sA + W_A;                // [160][STRD] tf32 bits, (N x K)
    float*    sV2 = (float*)(sB + W_B);      // [64][128] raw fp32
    float*    sW2 = sV2 + W_V2;              // [20][128] w^2
    float*    sR1 = sW2 + W_W2;              // [20][STRD] r1, padded
    float*    sR2 = sR1 + W_R1;              // [20][64]  r2

    const int tid  = threadIdx.x;
    const int wid  = tid >> 5;
    const int lane = tid & 31;
    const int b    = blockIdx.z;
    const int s0   = blockIdx.y * TM;
    const int t0   = blockIdx.x * TT;

    const int warp_m = wid >> 1;   // 0..3
    const int warp_n = wid & 1;    // 0..1
    const int grp    = lane >> 2;  // 0..7
    const int thr4   = lane & 3;   // 0..3

    const float* v1p = v1 + ((size_t)b * S_ + s0) * H_;
    const float* v2p = v2 + ((size_t)b * S_ + t0) * H_;

    // ---- prologue ----
    // A tile: tf32(v1), row-major [r][k], padded stride
    #pragma unroll
    for (int k = 0; k < 16; ++k) {
        const int task = tid + k * 256;            // 4096 float4 tasks
        const int r  = task >> 5;
        const int h4 = task & 31;
        const float4 v = *(const float4*)(v1p + r * H_ + h4 * 4);
        uint4 o;
        o.x = tf32r(v.x); o.y = tf32r(v.y); o.z = tf32r(v.z); o.w = tf32r(v.w);
        *(uint4*)(sA + r * STRD + h4 * 4) = o;     // 16B aligned (528r + 16h4)
    }
    // raw v2 tile
    #pragma unroll
    for (int k = 0; k < 8; ++k) {
        const int task = tid + k * 256;            // 2048 float4 tasks
        ((float4*)sV2)[task] = *(const float4*)(v2p + (task >> 5) * H_ + (task & 31) * 4);
    }
    // w^2
    for (int i = tid; i < W_W2 / 4; i += 256) {
        const float4 wv = ((const float4*)w)[i];
        float4 o; o.x = wv.x * wv.x; o.y = wv.y * wv.y; o.z = wv.z * wv.z; o.w = wv.w * wv.w;
        ((float4*)sW2)[i] = o;
    }
    // r1 (padded stride), r2
    for (int i = tid; i < L_ * TM; i += 256) {
        const int l = i >> 7, sl = i & 127;
        sR1[l * STRD + sl] = g_r1[((size_t)b * L_ + l) * S_ + s0 + sl];
    }
    for (int i = tid; i < L_ * TT; i += 256) {
        const int l = i >> 6, tl = i & 63;
        sR2[i] = g_r2[((size_t)b * L_ + l) * S_ + t0 + tl];
    }
    __syncthreads();

    const size_t bS = (size_t)b * S_;

    #pragma unroll 1
    for (int chunk = 0; chunk < NCHUNKS; ++chunk) {
        // ---- build B'' chunk: row n = t_sub*20 + l, val = tf32(v2 * w^2 * r2) ----
        #pragma unroll
        for (int k = 0; k < 20; ++k) {
            const int task = tid + k * 256;        // 5120 float4 tasks (160 x 32)
            const int n  = task >> 5;              // 0..159
            const int h4 = task & 31;
            const int ts = n / 20;
            const int l  = n - ts * 20;
            const float4 v  = ((const float4*)sV2)[(chunk * 8 + ts) * 32 + h4];
            const float4 wv = ((const float4*)sW2)[l * 32 + h4];
            const float  r2 = sR2[l * TT + chunk * 8 + ts];
            uint4 o;
            o.x = tf32r(v.x * wv.x * r2); o.y = tf32r(v.y * wv.y * r2);
            o.z = tf32r(v.z * wv.z * r2); o.w = tf32r(v.w * wv.w * r2);
            *(uint4*)(sB + n * STRD + h4 * 4) = o;
        }
        __syncthreads();

        // ---- K-loop ----
        float acc[2][10][4];
        #pragma unroll
        for (int i = 0; i < 2; ++i)
            #pragma unroll
            for (int j = 0; j < 10; ++j)
                #pragma unroll
                for (int q = 0; q < 4; ++q) acc[i][j][q] = 0.f;

        #pragma unroll 4
        for (int k8 = 0; k8 < 16; ++k8) {
            const int kk = k8 * 8 + thr4;
            uint32_t af[2][4];
            #pragma unroll
            for (int i = 0; i < 2; ++i) {
                const int row = warp_m * 32 + i * 16 + grp;
                af[i][0] = sA[row * STRD + kk];
                af[i][1] = sA[(row + 8) * STRD + kk];
                af[i][2] = sA[row * STRD + kk + 4];
                af[i][3] = sA[(row + 8) * STRD + kk + 4];
            }
            uint32_t bf[10][2];
            #pragma unroll
            for (int j = 0; j < 10; ++j) {
                const int n = warp_n * 80 + j * 8 + grp;
                bf[j][0] = sB[n * STRD + kk];
                bf[j][1] = sB[n * STRD + kk + 4];
            }
            #pragma unroll
            for (int i = 0; i < 2; ++i)
                #pragma unroll
                for (int j = 0; j < 10; ++j)
                    mma_tf32(acc[i][j][0], acc[i][j][1], acc[i][j][2], acc[i][j][3],
                             af[i][0], af[i][1], af[i][2], af[i][3], bf[j][0], bf[j][1]);
        }

        // ---- epilogue: scale by r1, store float2 pairs (dense in c) ----
        #pragma unroll
        for (int i = 0; i < 2; ++i) {
            const int rowl = warp_m * 32 + i * 16 + grp;
            const float* r1b = sR1 + rowl;
            float* orow0 = out + ((bS + s0 + rowl) * S_ + t0 + chunk * 8) * L_;
            float* orow1 = orow0 + (size_t)8 * S_ * L_;
            #pragma unroll
            for (int j = 0; j < 10; ++j) {
                const int c  = warp_n * 80 + j * 8 + 2 * thr4;   // even
                const int ts = c / 20;
                const int l  = c - ts * 20;                       // pair (l, l+1) same t
                const float r1_0 = r1b[l * STRD];
                const float r1_1 = r1b[(l + 1) * STRD];
                const float r8_0 = r1b[l * STRD + 8];
                const float r8_1 = r1b[(l + 1) * STRD + 8];
                float2 v0, v1r;
                v0.x  = acc[i][j][0] * r1_0;  v0.y  = acc[i][j][1] * r1_1;
                v1r.x = acc[i][j][2] * r8_0;  v1r.y = acc[i][j][3] * r8_1;
                *(float2*)(orow0 + c) = v0;    // out offset within row == c
                *(float2*)(orow1 + c) = v1r;
            }
        }
        __syncthreads();   // sB free before next build
    }
}

// ---------------- launch ----------------
extern "C" void kernel_launch(void* const* d_in, const int* in_sizes, int n_in,
                              void* d_out, int out_size) {
    (void)in_sizes; (void)n_in; (void)out_size;
    const float* v1 = (const float*)d_in[0];   // (16, 512, 128)
    const float* v2 = (const float*)d_in[1];   // (16, 512, 128)
    const float* w  = (const float*)d_in[2];   // (20, 128)
    float* out = (float*)d_out;                // (16, 512, 512, 20)

    cudaFuncSetAttribute(match_kernel, cudaFuncAttributeMaxDynamicSharedMemorySize, SMEM_BYTES);

    dim3 ngrid((B_ * S_ * 32) / 256, 2);       // merged v1/v2 norm pass
    norm_kernel<<<ngrid, 256>>>(v1, v2, w);

    dim3 grid(S_ / TT, S_ / TM, B_);           // (8, 4, 16) = 512 CTAs
    match_kernel<<<grid, 256, SMEM_BYTES>>>(v1, v2, w, out);
}

// round 6
// speedup vs baseline: 3.3046x; 1.0726x over previous
#include <cuda_runtime.h>
#include <cstdint>

#define B_   16
#define S_   512
#define H_   128
#define L_   20
#define TM   128          // s per CTA
#define TT   64           // t per CTA
#define NCH  160          // MMA N per chunk = 8 t x 20 l (l fastest)
#define NCHUNKS 8
#define STRD 132          // padded smem row stride (words)

// smem word offsets
#define W_A   (TM * STRD)            // 16896
#define W_B   (NCH * STRD)           // 21120
#define W_V2  (TT * H_)              // 8192
#define W_W2  (L_ * H_)              // 2560
#define W_R1  (L_ * STRD)            // 2640
#define W_R2  (L_ * TT)              // 1280
#define SMEM_WORDS (W_A + W_B + W_V2 + W_W2 + W_R1 + W_R2)
#define SMEM_BYTES (SMEM_WORDS * 4)  // 210752

__device__ float g_r1[B_ * L_ * S_];
__device__ float g_r2[B_ * L_ * S_];

static __device__ __forceinline__ uint32_t tf32r(float x) {
    uint32_t r;
    asm("cvt.rna.tf32.f32 %0, %1;" : "=r"(r) : "f"(x));
    return r;
}
static __device__ __forceinline__ void mma_tf32(float& c0, float& c1, float& c2, float& c3,
                                                uint32_t a0, uint32_t a1, uint32_t a2, uint32_t a3,
                                                uint32_t b0, uint32_t b1) {
    asm volatile("mma.sync.aligned.m16n8k8.row.col.f32.tf32.tf32.f32 "
                 "{%0,%1,%2,%3}, {%4,%5,%6,%7}, {%8,%9}, {%0,%1,%2,%3};"
                 : "+f"(c0), "+f"(c1), "+f"(c2), "+f"(c3)
                 : "r"(a0), "r"(a1), "r"(a2), "r"(a3), "r"(b0), "r"(b1));
}
static __device__ __forceinline__ void ldsm4(uint32_t& r0, uint32_t& r1, uint32_t& r2, uint32_t& r3,
                                             uint32_t addr) {
    asm volatile("ldmatrix.sync.aligned.m8n8.x4.shared.b16 {%0,%1,%2,%3}, [%4];"
                 : "=r"(r0), "=r"(r1), "=r"(r2), "=r"(r3) : "r"(addr));
}
static __device__ __forceinline__ void ldsm2(uint32_t& r0, uint32_t& r1, uint32_t addr) {
    asm volatile("ldmatrix.sync.aligned.m8n8.x2.shared.b16 {%0,%1}, [%2];"
                 : "=r"(r0), "=r"(r1) : "r"(addr));
}
static __device__ __forceinline__ uint32_t smem_u32(const void* p) {
    return (uint32_t)__cvta_generic_to_shared(p);
}

// ---------------- kernel 1: reciprocal weighted norms ----------------
__global__ void norm_kernel(const float* __restrict__ v1, const float* __restrict__ v2,
                            const float* __restrict__ w) {
    const float* v  = blockIdx.y ? v2 : v1;
    float*       rg = blockIdx.y ? g_r2 : g_r1;
    const int gwarp = (blockIdx.x * blockDim.x + threadIdx.x) >> 5;
    const int lane  = threadIdx.x & 31;
    if (gwarp >= B_ * S_) return;

    const float4 xv = ((const float4*)(v + (size_t)gwarp * H_))[lane];
    const int b = gwarp >> 9;
    const int s = gwarp & (S_ - 1);

    #pragma unroll
    for (int l = 0; l < L_; l += 2) {
        const float4 w0 = ((const float4*)(w + l * H_))[lane];
        const float4 w1 = ((const float4*)(w + (l + 1) * H_))[lane];
        float t, p0, p1;
        t = w0.x * xv.x; p0  = t * t;  t = w1.x * xv.x; p1  = t * t;
        t = w0.y * xv.y; p0 += t * t;  t = w1.y * xv.y; p1 += t * t;
        t = w0.z * xv.z; p0 += t * t;  t = w1.z * xv.z; p1 += t * t;
        t = w0.w * xv.w; p0 += t * t;  t = w1.w * xv.w; p1 += t * t;
        #pragma unroll
        for (int o = 16; o; o >>= 1) {
            p0 += __shfl_xor_sync(0xffffffffu, p0, o);
            p1 += __shfl_xor_sync(0xffffffffu, p1, o);
        }
        if (lane == 0) {
            rg[((size_t)b * L_ + l) * S_ + s]     = rsqrtf(fmaxf(p0, 1e-24f));
            rg[((size_t)b * L_ + l + 1) * S_ + s] = rsqrtf(fmaxf(p1, 1e-24f));
        }
    }
}

// ---------------- kernel 2: tf32 mma.sync GEMM, l-in-N, ldmatrix ----------------
// 512 threads = 16 warps: warp_m = wid>>2 (4 along M: 32 rows each = 2 m16),
// warp_n = wid&3 (4 along N: 40 cols each = 5 n8). K=128 in 16 k8 steps.
__global__ void __launch_bounds__(512, 1)
match_kernel(const float* __restrict__ v1, const float* __restrict__ v2,
             const float* __restrict__ w, float* __restrict__ out) {
    extern __shared__ uint32_t smu[];
    uint32_t* sA  = smu;                     // [128][STRD] tf32 bits (M x K)
    uint32_t* sB  = sA + W_A;                // [160][STRD] tf32 bits (N x K)
    float*    sV2 = (float*)(sB + W_B);      // [64][128] raw fp32
    float*    sW2 = sV2 + W_V2;              // [20][128] w^2
    float*    sR1 = sW2 + W_W2;              // [20][STRD] r1, padded
    float*    sR2 = sR1 + W_R1;              // [20][64]  r2

    const int tid  = threadIdx.x;
    const int wid  = tid >> 5;
    const int lane = tid & 31;
    const int b    = blockIdx.z;
    const int s0   = blockIdx.y * TM;
    const int t0   = blockIdx.x * TT;

    const int warp_m = wid >> 2;   // 0..3
    const int warp_n = wid & 3;    // 0..3
    const int grp    = lane >> 2;  // 0..7
    const int thr4   = lane & 3;   // 0..3

    const float* v1p = v1 + ((size_t)b * S_ + s0) * H_;
    const float* v2p = v2 + ((size_t)b * S_ + t0) * H_;

    // ---- prologue ----
    #pragma unroll
    for (int k = 0; k < 8; ++k) {
        const int task = tid + k * 512;            // 4096 float4 tasks
        const int r  = task >> 5;
        const int h4 = task & 31;
        const float4 v = *(const float4*)(v1p + r * H_ + h4 * 4);
        uint4 o;
        o.x = tf32r(v.x); o.y = tf32r(v.y); o.z = tf32r(v.z); o.w = tf32r(v.w);
        *(uint4*)(sA + r * STRD + h4 * 4) = o;
    }
    #pragma unroll
    for (int k = 0; k < 4; ++k) {
        const int task = tid + k * 512;            // 2048 float4 tasks
        ((float4*)sV2)[task] = *(const float4*)(v2p + (task >> 5) * H_ + (task & 31) * 4);
    }
    for (int i = tid; i < W_W2 / 4; i += 512) {
        const float4 wv = ((const float4*)w)[i];
        float4 o; o.x = wv.x * wv.x; o.y = wv.y * wv.y; o.z = wv.z * wv.z; o.w = wv.w * wv.w;
        ((float4*)sW2)[i] = o;
    }
    for (int i = tid; i < L_ * TM; i += 512) {
        const int l = i >> 7, sl = i & 127;
        sR1[l * STRD + sl] = g_r1[((size_t)b * L_ + l) * S_ + s0 + sl];
    }
    for (int i = tid; i < L_ * TT; i += 512) {
        const int l = i >> 6, tl = i & 63;
        sR2[i] = g_r2[((size_t)b * L_ + l) * S_ + t0 + tl];
    }
    __syncthreads();

    // ---- ldmatrix per-thread base addresses (byte, shared window) ----
    const uint32_t sA_u = smem_u32(sA);
    const uint32_t sB_u = smem_u32(sB);
    // A x4 tile at (R + lane&15, col + 4*(lane>>4))
    uint32_t a_base[2];
    #pragma unroll
    for (int i = 0; i < 2; ++i) {
        const int row = warp_m * 32 + i * 16 + (lane & 15);
        a_base[i] = sA_u + (uint32_t)(row * STRD + ((lane >> 4) << 2)) * 4u;
    }
    // B x4 pair tiles at rows Nj + (lane&7) + 8*(lane>>4), col + 4*((lane>>3)&1)
    uint32_t b_base[2];
    #pragma unroll
    for (int jp = 0; jp < 2; ++jp) {
        const int row = warp_n * 40 + jp * 16 + (lane & 7) + ((lane >> 4) << 3);
        b_base[jp] = sB_u + (uint32_t)(row * STRD + (((lane >> 3) & 1) << 2)) * 4u;
    }
    // B x2 single tile (j=4): rows N4 + (lane&7), col + 4*((lane>>3)&1); lanes 16-31 unused
    const uint32_t b_base4 = sB_u +
        (uint32_t)((warp_n * 40 + 32 + (lane & 7)) * STRD + (((lane >> 3) & 1) << 2)) * 4u;

    const size_t bS = (size_t)b * S_;

    #pragma unroll 1
    for (int chunk = 0; chunk < NCHUNKS; ++chunk) {
        // ---- build B'' chunk: row n = t_sub*20 + l, val = tf32(v2 * w^2) ----
        #pragma unroll
        for (int k = 0; k < 10; ++k) {
            const int task = tid + k * 512;        // 5120 float4 tasks
            const int n  = task >> 5;              // 0..159
            const int h4 = task & 31;
            const int ts = n / 20;
            const int l  = n - ts * 20;
            const float4 v  = ((const float4*)sV2)[(chunk * 8 + ts) * 32 + h4];
            const float4 wv = ((const float4*)sW2)[l * 32 + h4];
            uint4 o;
            o.x = tf32r(v.x * wv.x); o.y = tf32r(v.y * wv.y);
            o.z = tf32r(v.z * wv.z); o.w = tf32r(v.w * wv.w);
            *(uint4*)(sB + n * STRD + h4 * 4) = o;
        }
        __syncthreads();

        // ---- K-loop ----
        float acc[2][5][4];
        #pragma unroll
        for (int i = 0; i < 2; ++i)
            #pragma unroll
            for (int j = 0; j < 5; ++j)
                #pragma unroll
                for (int q = 0; q < 4; ++q) acc[i][j][q] = 0.f;

        #pragma unroll
        for (int k8 = 0; k8 < 16; ++k8) {
            const uint32_t koff = (uint32_t)(k8 * 32);   // 8 words
            uint32_t af[2][4];
            ldsm4(af[0][0], af[0][1], af[0][2], af[0][3], a_base[0] + koff);
            ldsm4(af[1][0], af[1][1], af[1][2], af[1][3], a_base[1] + koff);
            uint32_t bf[5][2];
            ldsm4(bf[0][0], bf[0][1], bf[1][0], bf[1][1], b_base[0] + koff);
            ldsm4(bf[2][0], bf[2][1], bf[3][0], bf[3][1], b_base[1] + koff);
            ldsm2(bf[4][0], bf[4][1], b_base4 + koff);
            #pragma unroll
            for (int i = 0; i < 2; ++i)
                #pragma unroll
                for (int j = 0; j < 5; ++j)
                    mma_tf32(acc[i][j][0], acc[i][j][1], acc[i][j][2], acc[i][j][3],
                             af[i][0], af[i][1], af[i][2], af[i][3], bf[j][0], bf[j][1]);
        }

        // ---- epilogue: out = acc * r1[l,s] * r2[l,t], dense float2 stores ----
        #pragma unroll
        for (int i = 0; i < 2; ++i) {
            const int rowl = warp_m * 32 + i * 16 + grp;
            float* orow0 = out + ((bS + s0 + rowl) * S_ + t0 + chunk * 8) * L_;
            float* orow1 = orow0 + (size_t)8 * S_ * L_;
            #pragma unroll
            for (int j = 0; j < 5; ++j) {
                const int c  = warp_n * 40 + j * 8 + 2 * thr4;   // even; l = c mod 20 even
                const int ts = c / 20;
                const int l  = c - ts * 20;
                const float r2_0 = sR2[l * TT + chunk * 8 + ts];
                const float r2_1 = sR2[(l + 1) * TT + chunk * 8 + ts];
                const float s00 = sR1[l * STRD + rowl] * r2_0;
                const float s01 = sR1[(l + 1) * STRD + rowl] * r2_1;
                const float s10 = sR1[l * STRD + rowl + 8] * r2_0;
                const float s11 = sR1[(l + 1) * STRD + rowl + 8] * r2_1;
                float2 v0, v1r;
                v0.x  = acc[i][j][0] * s00;  v0.y  = acc[i][j][1] * s01;
                v1r.x = acc[i][j][2] * s10;  v1r.y = acc[i][j][3] * s11;
                *(float2*)(orow0 + c) = v0;
                *(float2*)(orow1 + c) = v1r;
            }
        }
        __syncthreads();   // sB free before next build
    }
}

// ---------------- launch ----------------
extern "C" void kernel_launch(void* const* d_in, const int* in_sizes, int n_in,
                              void* d_out, int out_size) {
    (void)in_sizes; (void)n_in; (void)out_size;
    const float* v1 = (const float*)d_in[0];   // (16, 512, 128)
    const float* v2 = (const float*)d_in[1];   // (16, 512, 128)
    const float* w  = (const float*)d_in[2];   // (20, 128)
    float* out = (float*)d_out;                // (16, 512, 512, 20)

    cudaFuncSetAttribute(match_kernel, cudaFuncAttributeMaxDynamicSharedMemorySize, SMEM_BYTES);

    dim3 ngrid((B_ * S_ * 32) / 256, 2);
    norm_kernel<<<ngrid, 256>>>(v1, v2, w);

    dim3 grid(S_ / TT, S_ / TM, B_);           // (8, 4, 16) = 512 CTAs
    match_kernel<<<grid, 512, SMEM_BYTES>>>(v1, v2, w, out);
}